// round 2
// baseline (speedup 1.0000x reference)
#include <cuda_runtime.h>

// Problem constants
#define T_STEPS 2048
#define B_TOT   256
#define H_DIM   512
#define D_IN    529            // 16 (x) + 512 (h) + 1 (cost)
#define STRIDE  564            // padded row stride in floats (16B-word stride 141, odd -> conflict-free)
#define NW      141            // 16B words per row
#define WPT     35             // 16B words per j-chunk (4 chunks * 35 = 140 words >= 133 data words)
#define CTAS_PER_CL 8
#define B_PER_CL    16
#define ROWS_PER_CTA 64
#define NTHREADS 256

// ping-pong hidden-state buffers (L2 resident, 1MB total)
__device__ float g_hbuf[2][B_TOT * H_DIM];

__device__ __forceinline__ void ffma2(unsigned long long &d, unsigned long long a, unsigned long long b) {
    // packed dual fp32 FMA: d.lo += a.lo*b.lo ; d.hi += a.hi*b.hi
    asm("fma.rn.f32x2 %0, %1, %2, %0;" : "+l"(d) : "l"(a), "l"(b));
}

__device__ __forceinline__ float unpack_sum(unsigned long long v) {
    float lo = __uint_as_float((unsigned)(v & 0xffffffffull));
    float hi = __uint_as_float((unsigned)(v >> 32));
    return lo + hi;
}

extern "C" __global__ void __launch_bounds__(NTHREADS, 1) __cluster_dims__(CTAS_PER_CL, 1, 1)
rnn_scan_kernel(const float* __restrict__ x,       // [B, T, 16]
                const float* __restrict__ hidden,  // [B, 512]
                const float* __restrict__ cost,    // [B, T]
                const float* __restrict__ Wo,      // [1, 529]
                const float* __restrict__ Wh,      // [512, 529]
                float* __restrict__ out)           // [B*T] outs, then [B*512] h_final
{
    extern __shared__ float smem[];
    float* W_s  = smem;                                // 64 x 564
    float* in_s = smem + ROWS_PER_CTA * STRIDE;        // 16 x 564 : [x(16)|h(512)|c(1)|zeros]
    float* Wo_s = in_s + B_PER_CL * STRIDE;            // 564

    const int tid   = threadIdx.x;
    const int crank = blockIdx.x & (CTAS_PER_CL - 1);  // rank within cluster
    const int clid  = blockIdx.x >> 3;                 // cluster id (0..15)
    const int bbase = clid * B_PER_CL;                 // global batch base for this cluster
    const int row0  = crank * ROWS_PER_CTA;            // H rows owned by this CTA

    // ---- one-time: load W chunk (zero-padded), Wo, zero-pad in_s tails ----
    for (int idx = tid; idx < ROWS_PER_CTA * STRIDE; idx += NTHREADS) {
        int r = idx / STRIDE;
        int c = idx - r * STRIDE;
        W_s[idx] = (c < D_IN) ? Wh[(size_t)(row0 + r) * D_IN + c] : 0.0f;
    }
    for (int idx = tid; idx < STRIDE; idx += NTHREADS)
        Wo_s[idx] = (idx < D_IN) ? Wo[idx] : 0.0f;
    for (int z = tid; z < B_PER_CL * (STRIDE - D_IN); z += NTHREADS) {
        int b = z / (STRIDE - D_IN);
        int c = D_IN + (z - b * (STRIDE - D_IN));
        in_s[b * STRIDE + c] = 0.0f;
    }
    __syncthreads();

    // compute-phase thread mapping: tid = (i4 * 4 + b4) * 4 + jc
    const int jc    = tid & 3;        // j-chunk (reduction split, shfl-reduced)
    const int idx64 = tid >> 2;
    const int b4    = idx64 & 3;      // batch block (4 rows)
    const int i4    = idx64 >> 2;     // output-row block (4 rows)

    // staging mapping: 16 threads per batch row
    const int hb = tid >> 4;
    const int hq = tid & 15;

    for (int t = 0; t < T_STEPS; ++t) {
        // ---- stage inter = [x_t | h | c_t] into in_s ----
        {
            const float* hsrc = (t == 0)
                ? (hidden + (size_t)(bbase + hb) * H_DIM)
                : (g_hbuf[(t + 1) & 1] + (size_t)(bbase + hb) * H_DIM);
            const float4* s4 = (const float4*)(hsrc + hq * 32);
            float4* d4 = (float4*)(in_s + hb * STRIDE + 16 + hq * 32);
            #pragma unroll
            for (int k = 0; k < 8; ++k) d4[k] = __ldcg(s4 + k);
        }
        if (tid < B_PER_CL) {
            int b = tid;
            const float4* xp = (const float4*)(x + ((size_t)(bbase + b) * T_STEPS + t) * 16);
            float4* dx = (float4*)(in_s + b * STRIDE);
            dx[0] = xp[0]; dx[1] = xp[1]; dx[2] = xp[2]; dx[3] = xp[3];
            in_s[b * STRIDE + 528] = cost[(size_t)(bbase + b) * T_STEPS + t];
        }
        __syncthreads();

        // ---- o_t = Wo . inter  (cluster CTA 0 only; uses pre-update h) ----
        if (crank == 0) {
            int b = tid >> 4, js = tid & 15;
            const ulonglong2* wop = (const ulonglong2*)Wo_s;
            const ulonglong2* hp  = (const ulonglong2*)(in_s + b * STRIDE);
            unsigned long long acc = 0ull;
            int w0 = js * 9;
            int w1 = min(NW, w0 + 9);
            for (int w = w0; w < w1; ++w) {
                ulonglong2 a = wop[w], h = hp[w];
                ffma2(acc, a.x, h.x);
                ffma2(acc, a.y, h.y);
            }
            float r = unpack_sum(acc);
            r += __shfl_xor_sync(0xffffffffu, r, 1);
            r += __shfl_xor_sync(0xffffffffu, r, 2);
            r += __shfl_xor_sync(0xffffffffu, r, 4);
            r += __shfl_xor_sync(0xffffffffu, r, 8);
            if (js == 0) out[(size_t)(bbase + b) * T_STEPS + t] = r;
        }

        // ---- main matvec: h_new[b, i] = W[i,:] . inter[b,:]  (4i x 4b tile / thread) ----
        unsigned long long acc[4][4];
        #pragma unroll
        for (int a = 0; a < 4; ++a)
            #pragma unroll
            for (int c = 0; c < 4; ++c) acc[a][c] = 0ull;

        const float* wb  = W_s  + (i4 * 4) * STRIDE + jc * 140;
        const float* hb2 = in_s + (b4 * 4) * STRIDE + jc * 140;

        #pragma unroll 5
        for (int k = 0; k < WPT; ++k) {
            ulonglong2 wv[4], hv[4];
            #pragma unroll
            for (int a = 0; a < 4; ++a)
                wv[a] = *(const ulonglong2*)(wb + a * STRIDE + 4 * k);
            #pragma unroll
            for (int c = 0; c < 4; ++c)
                hv[c] = *(const ulonglong2*)(hb2 + c * STRIDE + 4 * k);
            #pragma unroll
            for (int a = 0; a < 4; ++a)
                #pragma unroll
                for (int c = 0; c < 4; ++c) {
                    ffma2(acc[a][c], wv[a].x, hv[c].x);
                    ffma2(acc[a][c], wv[a].y, hv[c].y);
                }
        }

        // ---- reduce across the 4 jc lanes (adjacent lanes) ----
        float rr[4][4];
        #pragma unroll
        for (int a = 0; a < 4; ++a)
            #pragma unroll
            for (int c = 0; c < 4; ++c) {
                float r = unpack_sum(acc[a][c]);
                r += __shfl_xor_sync(0xffffffffu, r, 1);
                r += __shfl_xor_sync(0xffffffffu, r, 2);
                rr[a][c] = r;
            }

        // ---- write h_new chunk (last step writes h_final region of out) ----
        if ((tid & 3) == 0) {
            float* hdst = (t == T_STEPS - 1) ? (out + (size_t)B_TOT * T_STEPS)
                                             : g_hbuf[t & 1];
            #pragma unroll
            for (int c = 0; c < 4; ++c) {
                int bl = b4 * 4 + c;
                float4 v = make_float4(rr[0][c], rr[1][c], rr[2][c], rr[3][c]);
                __stcg((float4*)(hdst + (size_t)(bbase + bl) * H_DIM + row0 + i4 * 4), v);
            }
        }

        // ---- cluster barrier: publish h_new (L2 via stcg) before next step reads ----
        asm volatile("barrier.cluster.arrive.aligned;" ::: "memory");
        asm volatile("barrier.cluster.wait.aligned;"   ::: "memory");
    }
}

extern "C" void kernel_launch(void* const* d_in, const int* in_sizes, int n_in,
                              void* d_out, int out_size) {
    const float* x      = (const float*)d_in[0];
    const float* hidden = (const float*)d_in[1];
    const float* cost   = (const float*)d_in[2];
    const float* Wo     = (const float*)d_in[3];
    const float* Wh     = (const float*)d_in[4];
    float* out = (float*)d_out;

    size_t smem = (size_t)(ROWS_PER_CTA * STRIDE + B_PER_CL * STRIDE + STRIDE) * sizeof(float);
    cudaFuncSetAttribute(rnn_scan_kernel, cudaFuncAttributeMaxDynamicSharedMemorySize, (int)smem);
    rnn_scan_kernel<<<128, NTHREADS, smem>>>(x, hidden, cost, Wo, Wh, out);
}